// round 1
// baseline (speedup 1.0000x reference)
#include <cuda_runtime.h>
#include <math_constants.h>

// Problem constants
#define Bn 128   // batch (both queries and docs)
#define Sn 32    // query tokens
#define Dn 128   // doc tokens
#define Hn 128   // hidden dim

// Scratch for the [B,B] score matrix (device global: no allocations allowed)
__device__ float g_scores[Bn * Bn];

// ---------------------------------------------------------------------------
// Kernel A: one CTA per (b, c) pair.
//   scores[b][c] = sum_s max_d  dot(Q[b,s,:], P[c,d,:])
// Shared memory (dynamic, 80KB):
//   Qt[h][s]  (Hn x Sn)  transposed query tile
//   Pt[h][d]  (Hn x Dn)  transposed doc tile
// 128 threads, each computes a 4s x 8d register tile (d split into two
// halves {4*di..}, {64+4*di..} so LDS.128 phases hit distinct banks).
// ---------------------------------------------------------------------------
extern "C" __global__ void __launch_bounds__(128, 2)
colbert_scores_kernel(const float* __restrict__ Q, const float* __restrict__ P)
{
    extern __shared__ float smem[];
    float* Qt = smem;             // [Hn][Sn]
    float* Pt = smem + Hn * Sn;   // [Hn][Dn]

    const int c = blockIdx.x;
    const int b = blockIdx.y;
    const int t = threadIdx.x;
    const int lane = t & 31;
    const int w = t >> 5;

    // ---- Load Q_b -> Qt[h][s] (lane = s, warp = h-chunk). Stores hit bank
    //      s == lane -> conflict free.
    {
        const float4* Qg = reinterpret_cast<const float4*>(
            Q + (size_t)b * Sn * Hn + (size_t)lane * Hn + w * 32);
        #pragma unroll
        for (int j = 0; j < 8; ++j) {
            float4 v = Qg[j];
            int h = w * 32 + 4 * j;
            Qt[(h + 0) * Sn + lane] = v.x;
            Qt[(h + 1) * Sn + lane] = v.y;
            Qt[(h + 2) * Sn + lane] = v.z;
            Qt[(h + 3) * Sn + lane] = v.w;
        }
    }

    // ---- Load P_c -> Pt[h][d] (thread = d row). Stores hit bank d%32 == lane
    //      -> conflict free. Each thread streams its own row (L1 absorbs
    //      the strided sectors; tile is L2-resident anyway).
    {
        const float4* Pg = reinterpret_cast<const float4*>(
            P + (size_t)c * Dn * Hn + (size_t)t * Hn);
        #pragma unroll 4
        for (int j = 0; j < 32; ++j) {
            float4 v = Pg[j];
            int h = 4 * j;
            Pt[(h + 0) * Dn + t] = v.x;
            Pt[(h + 1) * Dn + t] = v.y;
            Pt[(h + 2) * Dn + t] = v.z;
            Pt[(h + 3) * Dn + t] = v.w;
        }
    }
    __syncthreads();

    // ---- Mainloop: 4s x 8d register tile per thread
    const int d_idx = t & 15;        // 0..15
    const int s_idx = t >> 4;        // 0..7
    const int s0 = 4 * s_idx;
    const int dA = 4 * d_idx;        // lower-half d columns
    const int dB = 64 + 4 * d_idx;   // upper-half d columns

    float acc[4][8];
    #pragma unroll
    for (int i = 0; i < 4; ++i)
        #pragma unroll
        for (int j = 0; j < 8; ++j) acc[i][j] = 0.0f;

    #pragma unroll 4
    for (int h = 0; h < Hn; ++h) {
        float4 q  = *reinterpret_cast<const float4*>(&Qt[h * Sn + s0]);
        float4 pa = *reinterpret_cast<const float4*>(&Pt[h * Dn + dA]);
        float4 pb = *reinterpret_cast<const float4*>(&Pt[h * Dn + dB]);
        float qv[4] = {q.x, q.y, q.z, q.w};
        float pv[8] = {pa.x, pa.y, pa.z, pa.w, pb.x, pb.y, pb.z, pb.w};
        #pragma unroll
        for (int i = 0; i < 4; ++i)
            #pragma unroll
            for (int j = 0; j < 8; ++j)
                acc[i][j] = fmaf(qv[i], pv[j], acc[i][j]);
    }

    // ---- Epilogue: max over d (local 8, then shfl across the 16 d-lanes;
    //      xor offsets < 16 never cross the s-group boundary at lane bit 4),
    //      then sum the 4 s-rows this thread owns.
    float sum4 = 0.0f;
    #pragma unroll
    for (int i = 0; i < 4; ++i) {
        float m = acc[i][0];
        #pragma unroll
        for (int j = 1; j < 8; ++j) m = fmaxf(m, acc[i][j]);
        #pragma unroll
        for (int off = 8; off >= 1; off >>= 1)
            m = fmaxf(m, __shfl_xor_sync(0xffffffffu, m, off));
        sum4 += m;
    }

    __shared__ float part[8];
    if (d_idx == 0) part[s_idx] = sum4;
    __syncthreads();
    if (t == 0) {
        float tot = 0.0f;
        #pragma unroll
        for (int i = 0; i < 8; ++i) tot += part[i];
        g_scores[b * Bn + c] = tot;
    }
}

// ---------------------------------------------------------------------------
// Kernel B: loss = -mean_b( logits[b][b] - logsumexp_c logits[b][c] )
// with logits = scores / TEMPERATURE. One block, thread b handles row b.
// ---------------------------------------------------------------------------
extern "C" __global__ void colbert_loss_kernel(float* __restrict__ out)
{
    const int b = threadIdx.x;
    const float invT = 50.0f;  // 1 / 0.02

    float m = -CUDART_INF_F;
    for (int cc = 0; cc < Bn; ++cc)
        m = fmaxf(m, g_scores[b * Bn + cc] * invT);

    float se = 0.0f;
    for (int cc = 0; cc < Bn; ++cc)
        se += expf(g_scores[b * Bn + cc] * invT - m);

    float lse = m + logf(se);
    float term = g_scores[b * Bn + b] * invT - lse;  // logp of the diagonal

    __shared__ float red[Bn];
    red[b] = term;
    __syncthreads();
    #pragma unroll
    for (int off = Bn / 2; off > 0; off >>= 1) {
        if (b < off) red[b] += red[b + off];
        __syncthreads();
    }
    if (b == 0) out[0] = -red[0] / (float)Bn;
}

// ---------------------------------------------------------------------------
extern "C" void kernel_launch(void* const* d_in, const int* in_sizes, int n_in,
                              void* d_out, int out_size)
{
    const float* Q = (const float*)d_in[0];  // [B, S, H] fp32
    const float* P = (const float*)d_in[1];  // [B, D, H] fp32
    float* out = (float*)d_out;              // scalar fp32 loss

    const int smem_bytes = (Hn * Sn + Hn * Dn) * (int)sizeof(float);  // 80KB
    cudaFuncSetAttribute(colbert_scores_kernel,
                         cudaFuncAttributeMaxDynamicSharedMemorySize, smem_bytes);

    dim3 grid(Bn, Bn);
    colbert_scores_kernel<<<grid, 128, smem_bytes>>>(Q, P);
    colbert_loss_kernel<<<1, Bn>>>(out);
}

// round 3
// speedup vs baseline: 6.2872x; 6.2872x over previous
#include <cuda_runtime.h>
#include <math_constants.h>
#include <cstdint>

#define Bn 128
#define Sn 32
#define Dn 128
#define Hn 128
#define STRIDE 132            // words per smem row (conflict-free for all patterns)

__device__ float g_scores[Bn * Bn];

__device__ __forceinline__ uint32_t f2tf32(float x) {
    uint32_t r; asm("cvt.rna.tf32.f32 %0, %1;" : "=r"(r) : "f"(x)); return r;
}

// D += A(16x8,row) * B(8x8,col)  -- tf32, fp32 accum
__device__ __forceinline__ void mma8(float* d, const uint32_t* a, uint32_t b0, uint32_t b1) {
    asm volatile(
        "mma.sync.aligned.m16n8k8.row.col.f32.tf32.tf32.f32 "
        "{%0,%1,%2,%3}, {%4,%5,%6,%7}, {%8,%9}, {%0,%1,%2,%3};"
        : "+f"(d[0]), "+f"(d[1]), "+f"(d[2]), "+f"(d[3])
        : "r"(a[0]), "r"(a[1]), "r"(a[2]), "r"(a[3]), "r"(b0), "r"(b1));
}

// ---------------------------------------------------------------------------
// Tile staging: a 128x128 fp32 tile -> smem (tf32 bits), row stride 132 words.
// 256 threads; warp covers one row per j -> STS.128 conflict-free.
// ---------------------------------------------------------------------------
__device__ __forceinline__ void ldg_pass(const float4* __restrict__ g, int pass, int t, float4* st) {
    #pragma unroll
    for (int j = 0; j < 8; ++j) st[j] = g[pass * 2048 + j * 256 + t];
}
__device__ __forceinline__ void sts_pass(uint32_t* __restrict__ Bs, int pass, int t, const float4* st) {
    #pragma unroll
    for (int j = 0; j < 8; ++j) {
        int idx = pass * 2048 + j * 256 + t;
        int n = idx >> 5, k4 = idx & 31;
        uint4 w;
        w.x = f2tf32(st[j].x); w.y = f2tf32(st[j].y);
        w.z = f2tf32(st[j].z); w.w = f2tf32(st[j].w);
        *reinterpret_cast<uint4*>(Bs + n * STRIDE + k4 * 4) = w;
    }
}

// ---------------------------------------------------------------------------
// Scores: grid 128 = (mi = bid>>2: 128 A-rows, cg = bid&3: 32 c's).
// 8 warps: wm = wid>>1 (M=32 stripe -> exactly one b), wn = wid&1 (N=64 half).
// Warp tile: 2 mtiles x 8 ntiles of m16n8k8, K=128 (16 ksteps), acc in regs.
// ---------------------------------------------------------------------------
extern "C" __global__ void __launch_bounds__(256, 1)
colbert_scores_mma(const float* __restrict__ Q, const float* __restrict__ P)
{
    extern __shared__ __align__(16) uint32_t smem[];
    uint32_t* As  = smem;                       // [128][132]
    uint32_t* BsA = smem + 128 * STRIDE;        // B buffer 0
    uint32_t* BsB = smem + 2 * 128 * STRIDE;    // B buffer 1
    float* sm_rmax = reinterpret_cast<float*>(smem + 3 * 128 * STRIDE); // [2][2][128]

    const int t    = threadIdx.x;
    const int lane = t & 31;
    const int wid  = t >> 5;
    const int wm   = wid >> 1;       // 0..3
    const int wn   = wid & 1;        // 0..1
    const int mi   = blockIdx.x >> 2;
    const int cg   = blockIdx.x & 3;
    const int gid  = lane >> 2;      // groupID 0..7
    const int tig  = lane & 3;       // thread-in-group 0..3

    // ---- A tile (Q rows mi*128..+127) -> smem
    {
        const float4* g = reinterpret_cast<const float4*>(Q + (size_t)mi * 128 * Hn);
        float4 st[8];
        ldg_pass(g, 0, t, st); sts_pass(As, 0, t, st);
        ldg_pass(g, 1, t, st); sts_pass(As, 1, t, st);
    }
    // ---- B tile for first c
    const float4* Pg = reinterpret_cast<const float4*>(P);
    {
        const float4* g = Pg + (size_t)(cg * 32) * 4096;
        float4 st[8];
        ldg_pass(g, 0, t, st); sts_pass(BsA, 0, t, st);
        ldg_pass(g, 1, t, st); sts_pass(BsA, 1, t, st);
    }
    __syncthreads();

    const uint32_t* Abase = As + (wm * 32 + gid) * STRIDE + tig;

    for (int i = 0; i < 32; ++i) {
        const int c = cg * 32 + i;
        uint32_t* Bcur = (i & 1) ? BsB : BsA;
        uint32_t* Bnxt = (i & 1) ? BsA : BsB;
        const bool pre = (i + 1 < 32);
        const float4* gn = Pg + (size_t)(c + 1) * 4096;
        const uint32_t* Bbase = Bcur + (wn * 64 + gid) * STRIDE + tig;

        float acc[2][8][4];
        #pragma unroll
        for (int mt = 0; mt < 2; ++mt)
            #pragma unroll
            for (int nt = 0; nt < 8; ++nt)
                #pragma unroll
                for (int r = 0; r < 4; ++r) acc[mt][nt][r] = 0.0f;

        float4 st[8];
        if (pre) ldg_pass(gn, 0, t, st);   // overlap with first half of compute

        #pragma unroll
        for (int ks = 0; ks < 8; ++ks) {
            const int ko = ks * 8;
            uint32_t a[2][4];
            #pragma unroll
            for (int mt = 0; mt < 2; ++mt) {
                const uint32_t* p = Abase + mt * 16 * STRIDE + ko;
                a[mt][0] = p[0]; a[mt][1] = p[8 * STRIDE];
                a[mt][2] = p[4]; a[mt][3] = p[8 * STRIDE + 4];
            }
            #pragma unroll
            for (int nt = 0; nt < 8; ++nt) {
                const uint32_t* q = Bbase + nt * 8 * STRIDE + ko;
                uint32_t b0 = q[0], b1 = q[4];
                mma8(acc[0][nt], a[0], b0, b1);
                mma8(acc[1][nt], a[1], b0, b1);
            }
        }

        if (pre) { sts_pass(Bnxt, 0, t, st); ldg_pass(gn, 1, t, st); }

        #pragma unroll
        for (int ks = 8; ks < 16; ++ks) {
            const int ko = ks * 8;
            uint32_t a[2][4];
            #pragma unroll
            for (int mt = 0; mt < 2; ++mt) {
                const uint32_t* p = Abase + mt * 16 * STRIDE + ko;
                a[mt][0] = p[0]; a[mt][1] = p[8 * STRIDE];
                a[mt][2] = p[4]; a[mt][3] = p[8 * STRIDE + 4];
            }
            #pragma unroll
            for (int nt = 0; nt < 8; ++nt) {
                const uint32_t* q = Bbase + nt * 8 * STRIDE + ko;
                uint32_t b0 = q[0], b1 = q[4];
                mma8(acc[0][nt], a[0], b0, b1);
                mma8(acc[1][nt], a[1], b0, b1);
            }
        }

        if (pre) sts_pass(Bnxt, 1, t, st);

        // ---- epilogue: row max over this warp's 64 n-columns
        float* rbuf = sm_rmax + ((i & 1) * 2 + wn) * 128;
        #pragma unroll
        for (int mt = 0; mt < 2; ++mt) {
            float m0 = acc[mt][0][0], m1 = acc[mt][0][2];
            #pragma unroll
            for (int nt = 0; nt < 8; ++nt) {
                m0 = fmaxf(m0, fmaxf(acc[mt][nt][0], acc[mt][nt][1]));
                m1 = fmaxf(m1, fmaxf(acc[mt][nt][2], acc[mt][nt][3]));
            }
            m0 = fmaxf(m0, __shfl_xor_sync(0xffffffffu, m0, 1));
            m0 = fmaxf(m0, __shfl_xor_sync(0xffffffffu, m0, 2));
            m1 = fmaxf(m1, __shfl_xor_sync(0xffffffffu, m1, 1));
            m1 = fmaxf(m1, __shfl_xor_sync(0xffffffffu, m1, 2));
            if (tig == 0) {
                rbuf[wm * 32 + mt * 16 + gid]     = m0;
                rbuf[wm * 32 + mt * 16 + gid + 8] = m1;
            }
        }
        __syncthreads();

        // ---- combine the two n-halves, sum over s, write score (wn==0 warps)
        if (wn == 0) {
            const float* r0 = sm_rmax + ((i & 1) * 2 + 0) * 128;
            const float* r1 = sm_rmax + ((i & 1) * 2 + 1) * 128;
            float v = fmaxf(r0[wm * 32 + lane], r1[wm * 32 + lane]);
            #pragma unroll
            for (int off = 16; off; off >>= 1) v += __shfl_xor_sync(0xffffffffu, v, off);
            if (lane == 0) g_scores[(mi * 4 + wm) * Bn + c] = v;
        }
    }
}

// ---------------------------------------------------------------------------
// Loss: logits = scores/T; loss = -mean(diag(log_softmax)). 1024 threads.
// ---------------------------------------------------------------------------
extern "C" __global__ void colbert_loss_tc(float* __restrict__ out)
{
    __shared__ float sdiag[Bn];
    __shared__ float sterm[Bn];
    __shared__ float spart[4];
    const int t = threadIdx.x;
    const int row = t >> 3;
    const int j = t & 7;
    const float invT = 50.0f;

    const float4* rp = reinterpret_cast<const float4*>(&g_scores[row * Bn + j * 16]);
    float l[16];
    #pragma unroll
    for (int k4 = 0; k4 < 4; ++k4) {
        float4 v = rp[k4];
        l[k4 * 4 + 0] = v.x * invT;
        l[k4 * 4 + 1] = v.y * invT;
        l[k4 * 4 + 2] = v.z * invT;
        l[k4 * 4 + 3] = v.w * invT;
    }
    float m = l[0];
    #pragma unroll
    for (int k = 1; k < 16; ++k) m = fmaxf(m, l[k]);
    #pragma unroll
    for (int off = 1; off <= 4; off <<= 1) m = fmaxf(m, __shfl_xor_sync(0xffffffffu, m, off));
    float s = 0.0f;
    #pragma unroll
    for (int k = 0; k < 16; ++k) s += expf(l[k] - m);
    #pragma unroll
    for (int off = 1; off <= 4; off <<= 1) s += __shfl_xor_sync(0xffffffffu, s, off);
    #pragma unroll
    for (int k = 0; k < 16; ++k)
        if (j * 16 + k == row) sdiag[row] = l[k];
    __syncthreads();
    if (j == 0) sterm[row] = sdiag[row] - (m + logf(s));
    __syncthreads();
    if (t < 128) {
        float v = sterm[t];
        #pragma unroll
        for (int off = 16; off; off >>= 1) v += __shfl_xor_sync(0xffffffffu, v, off);
        if ((t & 31) == 0) spart[t >> 5] = v;
    }
    __syncthreads();
    if (t == 0) out[0] = -(spart[0] + spart[1] + spart[2] + spart[3]) / 128.0f;
}

// ---------------------------------------------------------------------------
extern "C" void kernel_launch(void* const* d_in, const int* in_sizes, int n_in,
                              void* d_out, int out_size)
{
    const float* Q = (const float*)d_in[0];  // [128, 32, 128]
    const float* P = (const float*)d_in[1];  // [128, 128, 128]
    float* out = (float*)d_out;

    const int smem_bytes = (3 * 128 * STRIDE) * 4 + 2 * 2 * 128 * 4;  // 204,800 B
    cudaFuncSetAttribute(colbert_scores_mma,
                         cudaFuncAttributeMaxDynamicSharedMemorySize, smem_bytes);

    colbert_scores_mma<<<128, 256, smem_bytes>>>(Q, P);
    colbert_loss_tc<<<1, 1024>>>(out);
}

// round 4
// speedup vs baseline: 10.9145x; 1.7360x over previous
#include <cuda_runtime.h>
#include <cuda_fp16.h>
#include <math_constants.h>
#include <cstdint>

#define Bn 128
#define Hn 128

__device__ float    g_scores[Bn * Bn];
__device__ unsigned g_cnt = 0;

// smem byte layout: A tile (fp16, 32KB) | B buf0 | B buf1 | rmax/reduce region
#define A_OFF      0
#define B_OFF(b)   (32768 + (b) * 32768)
#define R_OFF      (3 * 32768)
#define SMEM_BYTES (3 * 32768 + 2048)

__device__ __forceinline__ uint32_t smem_u32(const void* p) {
    uint32_t a;
    asm("{ .reg .u64 t; cvta.to.shared.u64 t, %1; cvt.u32.u64 %0, t; }" : "=r"(a) : "l"(p));
    return a;
}

__device__ __forceinline__ void ldsm4(uint32_t& r0, uint32_t& r1, uint32_t& r2, uint32_t& r3,
                                      uint32_t addr) {
    asm volatile("ldmatrix.sync.aligned.m8n8.x4.shared.b16 {%0,%1,%2,%3}, [%4];"
                 : "=r"(r0), "=r"(r1), "=r"(r2), "=r"(r3) : "r"(addr));
}

// D(16x8,f32) += A(16x16,f16) * B(16x8,f16)
__device__ __forceinline__ void mma16(float* d, const uint32_t* a, uint32_t b0, uint32_t b1) {
    asm volatile(
        "mma.sync.aligned.m16n8k16.row.col.f32.f16.f16.f32 "
        "{%0,%1,%2,%3}, {%4,%5,%6,%7}, {%8,%9}, {%0,%1,%2,%3};"
        : "+f"(d[0]), "+f"(d[1]), "+f"(d[2]), "+f"(d[3])
        : "r"(a[0]), "r"(a[1]), "r"(a[2]), "r"(a[3]), "r"(b0), "r"(b1));
}

// ---------------------------------------------------------------------------
// Staging: 128x128 fp32 tile -> fp16 smem, rows of 256B, 16B units XOR-swizzled
// by (row & 7). Split LDG / STS halves for overlap with compute.
// ---------------------------------------------------------------------------
__device__ __forceinline__ void ldg8(const float4* __restrict__ g, int pass, int t, float4* st) {
    #pragma unroll
    for (int j = 0; j < 8; ++j) st[j] = g[pass * 2048 + j * 256 + t];
}
__device__ __forceinline__ void sts8(char* sm, int pass, int t, const float4* st) {
    #pragma unroll
    for (int j = 0; j < 8; ++j) {
        int idx = pass * 2048 + j * 256 + t;
        int row = idx >> 5, c4 = idx & 31;
        __half2 h0 = __floats2half2_rn(st[j].x, st[j].y);
        __half2 h1 = __floats2half2_rn(st[j].z, st[j].w);
        uint2 w;
        w.x = *reinterpret_cast<uint32_t*>(&h0);
        w.y = *reinterpret_cast<uint32_t*>(&h1);
        int off = row * 256 + (((c4 >> 1) ^ (row & 7)) << 4) + ((c4 & 1) << 3);
        *reinterpret_cast<uint2*>(sm + off) = w;
    }
}

// ---------------------------------------------------------------------------
// Fused kernel: 128 CTAs of 256 threads. CTA (mi=bid>>2, cg=bid&3).
// Warps: wm=wid>>1 (M=32 stripe = one b), wn=wid&1 (N=64 half).
// A fragments register-resident across all 32 c-iterations.
// Last CTA (atomic counter) computes the softmax loss.
// ---------------------------------------------------------------------------
extern "C" __global__ void __launch_bounds__(256, 1)
colbert_fused(const float* __restrict__ Q, const float* __restrict__ P, float* __restrict__ out)
{
    extern __shared__ __align__(128) char smem[];
    const uint32_t sbase = smem_u32(smem);

    const int t    = threadIdx.x;
    const int lane = t & 31;
    const int wid  = t >> 5;
    const int wm   = wid >> 1;
    const int wn   = wid & 1;
    const int mi   = blockIdx.x >> 2;
    const int cg   = blockIdx.x & 3;
    const int gid  = lane >> 2;
    const int tig  = lane & 3;

    // ---- stage A (Q rows mi*128..+127) and B tile for first c
    float4 st[8];
    {
        const float4* Qg = reinterpret_cast<const float4*>(Q + (size_t)mi * 128 * Hn);
        ldg8(Qg, 0, t, st); sts8(smem + A_OFF, 0, t, st);
        ldg8(Qg, 1, t, st); sts8(smem + A_OFF, 1, t, st);
    }
    const float4* Pg = reinterpret_cast<const float4*>(P);
    {
        const float4* g0 = Pg + (size_t)(cg * 32) * 4096;
        ldg8(g0, 0, t, st); sts8(smem + B_OFF(0), 0, t, st);
        ldg8(g0, 1, t, st); sts8(smem + B_OFF(0), 1, t, st);
    }
    __syncthreads();

    // ---- A fragments into registers (once)
    uint32_t aF[2][8][4];
    {
        const int rA = wm * 32 + (lane & 15);   // row for this lane (per mt add 16)
        const int kqA = lane >> 4;              // k-quadrant unit bit
        #pragma unroll
        for (int mt = 0; mt < 2; ++mt) {
            const int row = rA + mt * 16;
            const uint32_t rowbase = sbase + A_OFF + row * 256;
            #pragma unroll
            for (int ks = 0; ks < 8; ++ks) {
                uint32_t addr = rowbase + (((2 * ks + kqA) ^ (row & 7)) << 4);
                ldsm4(aF[mt][ks][0], aF[mt][ks][1], aF[mt][ks][2], aF[mt][ks][3], addr);
            }
        }
    }

    const int rBl = (lane & 7) + ((lane >> 4) << 3);  // local n-row within 16-block
    const int kqB = (lane >> 3) & 1;

    for (int i = 0; i < 32; ++i) {
        const int c = cg * 32 + i;
        const uint32_t Bbase = sbase + B_OFF(i & 1);
        char* Bnxt = smem + B_OFF(1 - (i & 1));
        const bool pre = (i + 1 < 32);
        const float4* gn = Pg + (size_t)(c + 1) * 4096;

        float acc[2][8][4];
        #pragma unroll
        for (int mt = 0; mt < 2; ++mt)
            #pragma unroll
            for (int nt = 0; nt < 8; ++nt)
                #pragma unroll
                for (int r = 0; r < 4; ++r) acc[mt][nt][r] = 0.0f;

        if (pre) ldg8(gn, 0, t, st);

        #pragma unroll
        for (int ks = 0; ks < 8; ++ks) {
            uint32_t bF[4][4];
            #pragma unroll
            for (int np = 0; np < 4; ++np) {
                const int row = wn * 64 + np * 16 + rBl;
                uint32_t addr = Bbase + row * 256 + (((2 * ks + kqB) ^ (row & 7)) << 4);
                ldsm4(bF[np][0], bF[np][1], bF[np][2], bF[np][3], addr);
            }
            #pragma unroll
            for (int np = 0; np < 4; ++np) {
                #pragma unroll
                for (int mt = 0; mt < 2; ++mt) {
                    mma16(acc[mt][2 * np],     aF[mt][ks], bF[np][0], bF[np][1]);
                    mma16(acc[mt][2 * np + 1], aF[mt][ks], bF[np][2], bF[np][3]);
                }
            }
            if (ks == 3 && pre) { sts8(Bnxt, 0, t, st); ldg8(gn, 1, t, st); }
        }
        if (pre) sts8(Bnxt, 1, t, st);

        // ---- epilogue: per-row max over this warp's 64 n-cols
        float* rbuf = reinterpret_cast<float*>(smem + R_OFF) + ((i & 1) * 2 + wn) * 128;
        #pragma unroll
        for (int mt = 0; mt < 2; ++mt) {
            float m0 = acc[mt][0][0], m1 = acc[mt][0][2];
            #pragma unroll
            for (int nt = 0; nt < 8; ++nt) {
                m0 = fmaxf(m0, fmaxf(acc[mt][nt][0], acc[mt][nt][1]));
                m1 = fmaxf(m1, fmaxf(acc[mt][nt][2], acc[mt][nt][3]));
            }
            m0 = fmaxf(m0, __shfl_xor_sync(0xffffffffu, m0, 1));
            m0 = fmaxf(m0, __shfl_xor_sync(0xffffffffu, m0, 2));
            m1 = fmaxf(m1, __shfl_xor_sync(0xffffffffu, m1, 1));
            m1 = fmaxf(m1, __shfl_xor_sync(0xffffffffu, m1, 2));
            if (tig == 0) {
                rbuf[wm * 32 + mt * 16 + gid]     = m0;
                rbuf[wm * 32 + mt * 16 + 8 + gid] = m1;
            }
        }
        __syncthreads();

        if (wn == 0) {
            const float* r0 = reinterpret_cast<const float*>(smem + R_OFF) + (i & 1) * 2 * 128;
            const float* r1 = r0 + 128;
            float v = fmaxf(r0[wm * 32 + lane], r1[wm * 32 + lane]);
            #pragma unroll
            for (int off = 16; off; off >>= 1) v += __shfl_xor_sync(0xffffffffu, v, off);
            if (lane == 0) g_scores[(mi * 4 + wm) * Bn + c] = v;
        }
    }

    // ---- last CTA computes the loss
    __syncthreads();
    __threadfence();
    __shared__ unsigned s_rank;
    if (t == 0) s_rank = atomicAdd(&g_cnt, 1);
    __syncthreads();
    if (s_rank != 127) return;
    if (t == 0) atomicExch(&g_cnt, 0);   // reset for graph replay
    __threadfence();

    const int row = t >> 1, j = t & 1;
    const float4* rp = reinterpret_cast<const float4*>(&g_scores[row * Bn + j * 64]);
    float m = -CUDART_INF_F, diag = 0.0f;
    #pragma unroll
    for (int k4 = 0; k4 < 16; ++k4) {
        float4 v = rp[k4];
        m = fmaxf(m, fmaxf(fmaxf(v.x, v.y), fmaxf(v.z, v.w)));
        int cb = j * 64 + k4 * 4;
        if (row == cb + 0) diag = v.x;
        if (row == cb + 1) diag = v.y;
        if (row == cb + 2) diag = v.z;
        if (row == cb + 3) diag = v.w;
    }
    m = fmaxf(m, __shfl_xor_sync(0xffffffffu, m, 1));
    diag += __shfl_xor_sync(0xffffffffu, diag, 1);

    float s = 0.0f;
    #pragma unroll
    for (int k4 = 0; k4 < 16; ++k4) {
        float4 v = rp[k4];
        s += expf(50.0f * (v.x - m)) + expf(50.0f * (v.y - m)) +
             expf(50.0f * (v.z - m)) + expf(50.0f * (v.w - m));
    }
    s += __shfl_xor_sync(0xffffffffu, s, 1);

    float* sred = reinterpret_cast<float*>(smem + R_OFF);
    if (j == 0) sred[row] = 50.0f * diag - (50.0f * m + logf(s));
    __syncthreads();
    if (t < 128) {
        float v = sred[t];
        #pragma unroll
        for (int off = 16; off; off >>= 1) v += __shfl_xor_sync(0xffffffffu, v, off);
        if ((t & 31) == 0) sred[256 + (t >> 5)] = v;
    }
    __syncthreads();
    if (t == 0) out[0] = -(sred[256] + sred[257] + sred[258] + sred[259]) / 128.0f;
}

// ---------------------------------------------------------------------------
extern "C" void kernel_launch(void* const* d_in, const int* in_sizes, int n_in,
                              void* d_out, int out_size)
{
    const float* Q = (const float*)d_in[0];  // [128, 32, 128]
    const float* P = (const float*)d_in[1];  // [128, 128, 128]
    float* out = (float*)d_out;

    cudaFuncSetAttribute(colbert_fused,
                         cudaFuncAttributeMaxDynamicSharedMemorySize, SMEM_BYTES);
    colbert_fused<<<128, 256, SMEM_BYTES>>>(Q, P, out);
}